// round 4
// baseline (speedup 1.0000x reference)
#include <cuda_runtime.h>
#include <stdint.h>

#define NLAYERS 24
#define BATCH   512
#define RDIM    32
#define LQ      256
#define LOUT    257
#define NROWS   (NLAYERS*BATCH*RDIM)      /* 393216 rows */
#define NGROUPS (NROWS/4)                 /* 98304 groups of 4 rows */
#define CGROUPS 4                         /* groups per chunk */
#define CH_IN   (CGROUPS*1024)            /* 4096 floats in per chunk (16KB) */
#define CH_OUT  (CGROUPS*1028)            /* 4112 floats out per chunk */
#define NCHUNKS (NGROUPS/CGROUPS)         /* 24576 chunks */
#define NCOPYB  1184                      /* 148 SMs x 8 blocks */
#define FULLMASK 0xffffffffu

// ---------------- scratch (static device globals; no allocation) ----------------
__device__ float2 g_wT [NLAYERS*32*128];   // [l][j][row] -> (w_past, w_h)
__device__ float  g_f1T[NLAYERS*32*128];   // [l][j][k]

__device__ __forceinline__ float sigf(float v) { return 1.0f / (1.0f + __expf(-v)); }

__device__ __forceinline__ void cp_async16(void* smem_dst, const void* gmem_src) {
    unsigned s = (unsigned)__cvta_generic_to_shared(smem_dst);
    asm volatile("cp.async.cg.shared.global [%0], [%1], 16;" :: "r"(s), "l"(gmem_src));
}

// ---------------- K0: weight transposes for coalesced lane access ----------------
__global__ void prep_kernel(const float* __restrict__ conv_w,
                            const float* __restrict__ fc1_w) {
    int idx = blockIdx.x * blockDim.x + threadIdx.x;
    if (idx >= NLAYERS * 32 * 128) return;
    {
        // conv_w: [l][row(128)][j(32)][2]  (float2 index = (l*128+row)*32 + j)
        int l = idx / 4096, rem = idx & 4095, row = rem / 32, j = rem & 31;
        float2 v = ((const float2*)conv_w)[idx];
        g_wT[(l * 32 + j) * 128 + row] = v;
    }
    {
        // fc1_w: [k(128)][768];  dst [l][j][k], idx == (l*32+j)*128 + k
        int l = idx / 4096, rem = idx & 4095, j = rem >> 7, k = rem & 127;
        g_f1T[idx] = fc1_w[k * 768 + l * 32 + j];
    }
}

// ---------------- K1: recurrence + heads (64 blocks x 8 warps = 512 batches) ----
__global__ void __launch_bounds__(256) compute_kernel(
    const float* __restrict__ x,      const float* __restrict__ feat,
    const float* __restrict__ queues,
    const float* __restrict__ fc_h_w, const float* __restrict__ fc_h_b,
    const float* __restrict__ fc_c_w, const float* __restrict__ fc_c_b,
    const float* __restrict__ conv_b,
    const float* __restrict__ fc1_b,  const float* __restrict__ fc2_w,
    const float* __restrict__ fc2_b,
    float* __restrict__ out)
{
    int warp = threadIdx.x >> 5;
    int lane = threadIdx.x & 31;
    int b    = blockIdx.x * 8 + warp;

    float h, c;
    {
        float ha = fc_h_b[lane], ca = fc_c_b[lane];
        #pragma unroll
        for (int i = 0; i < 9; i++) {
            float wh = fc_h_w[lane * 9 + i];
            float wc = fc_c_w[lane * 9 + i];
            float v  = (i == 0) ? x[b] : feat[b * 8 + i - 1];
            ha += wh * v; ca += wc * v;
        }
        h = tanhf(ha); c = tanhf(ca);
    }
    // h BEFORE layer 0 -> t=256 column of layer 0's queue rows
    out[BATCH + (size_t)((0 * BATCH + b) * RDIM + lane) * LOUT + 256] = h;

    float y0 = 0.f, y1 = 0.f, y2 = 0.f, y3 = 0.f;

    // prefetch p for layer 0
    float p = __ldg(queues + (size_t)((0 * BATCH + b) * RDIM + lane) * LQ + (LQ - 1));

    #pragma unroll 1
    for (int l = 0; l < NLAYERS; l++) {
        // prefetch next layer's past value early (hides DRAM latency under j-loops)
        float pn = 0.f;
        if (l < NLAYERS - 1) {
            int dn = 1 << ((l + 1) & 7);
            pn = __ldg(queues + (size_t)(((l + 1) * BATCH + b) * RDIM + lane) * LQ + (LQ - dn));
        }

        float a0 = __ldg(conv_b + l * 128 +  0 + lane);
        float a1 = __ldg(conv_b + l * 128 + 32 + lane);
        float a2 = __ldg(conv_b + l * 128 + 64 + lane);
        float a3 = __ldg(conv_b + l * 128 + 96 + lane);

        const float2* wp = g_wT + l * 32 * 128;
        #pragma unroll 8
        for (int j = 0; j < 32; j++) {
            float pj = __shfl_sync(FULLMASK, p, j);
            float hj = __shfl_sync(FULLMASK, h, j);
            float2 w0 = wp[j * 128 +  0 + lane];
            float2 w1 = wp[j * 128 + 32 + lane];
            float2 w2 = wp[j * 128 + 64 + lane];
            float2 w3 = wp[j * 128 + 96 + lane];
            a0 += w0.x * pj + w0.y * hj;
            a1 += w1.x * pj + w1.y * hj;
            a2 += w2.x * pj + w2.y * hj;
            a3 += w3.x * pj + w3.y * hj;
        }
        c = sigf(a0) * c + tanhf(a1) * sigf(a2);
        h = sigf(a3) * tanhf(c);
        p = pn;

        if (l < NLAYERS - 1)
            out[BATCH + (size_t)(((l + 1) * BATCH + b) * RDIM + lane) * LOUT + 256] = h;

        const float* f1p = g_f1T + l * 32 * 128;
        #pragma unroll 8
        for (int j = 0; j < 32; j++) {
            float hj = __shfl_sync(FULLMASK, h, j);
            y0 += f1p[j * 128 +  0 + lane] * hj;
            y1 += f1p[j * 128 + 32 + lane] * hj;
            y2 += f1p[j * 128 + 64 + lane] * hj;
            y3 += f1p[j * 128 + 96 + lane] * hj;
        }
    }

    float sacc = fmaxf(y0 + fc1_b[ 0 + lane], 0.f) * fc2_w[ 0 + lane]
               + fmaxf(y1 + fc1_b[32 + lane], 0.f) * fc2_w[32 + lane]
               + fmaxf(y2 + fc1_b[64 + lane], 0.f) * fc2_w[64 + lane]
               + fmaxf(y3 + fc1_b[96 + lane], 0.f) * fc2_w[96 + lane];
    #pragma unroll
    for (int off = 16; off > 0; off >>= 1)
        sacc += __shfl_xor_sync(FULLMASK, sacc, off);
    if (lane == 0) out[b] = sacc + fc2_b[0];
}

// ---------------- K2: high-occupancy staged queue copy ----------------
__global__ void __launch_bounds__(256, 8) copy_kernel(
    const float* __restrict__ queues, float* __restrict__ out)
{
    __shared__ float s[CH_IN];   // 16 KB
    int tid = threadIdx.x;

    // precompute store mapping for this thread (within a 1028-float group)
    int e = 4 * tid;                                  // 0..1020
    int r = (e >= 257) + (e >= 514) + (e >= 771);
    int t = e - 257 * r;
    bool boundary = (tid == 64) | (tid == 128) | (tid == 192);

    for (int chunk = blockIdx.x; chunk < NCHUNKS; chunk += gridDim.x) {
        // load: 4096 floats = 1024 x 16B, dense, via cp.async (bypass L1/regs)
        const float4* in4 = (const float4*)queues + (size_t)chunk * 1024;
        #pragma unroll
        for (int k = 0; k < 4; k++)
            cp_async16(&s[(k * 256 + tid) * 4], in4 + k * 256 + tid);
        asm volatile("cp.async.commit_group;");
        asm volatile("cp.async.wait_group 0;");
        __syncthreads();

        // store: 4 groups x 1028 floats, dense STG.128 with 256->257 phase shift
        float* ob = out + BATCH + (size_t)chunk * CH_OUT;
        #pragma unroll
        for (int lg = 0; lg < CGROUPS; lg++) {
            float* op = ob + lg * 1028 + e;
            if (boundary) {
                #pragma unroll
                for (int j = 0; j < 4; j++) {
                    int ee = e + j;
                    int rr = (ee >= 257) + (ee >= 514) + (ee >= 771);
                    int tt = ee - 257 * rr;
                    if (tt < 256)
                        __stcs(op + j, s[lg * 1024 + rr * 256 + tt]);
                }
            } else {
                const float* sp = s + lg * 1024 + r * 256 + t;
                float4 v;
                v.x = sp[0]; v.y = sp[1]; v.z = sp[2]; v.w = sp[3];
                __stcs((float4*)op, v);
            }
        }
        // tail e=1024..1026 of each group (t=253..255; t=256 owned by compute)
        if (tid < CGROUPS) {
            float* op = ob + tid * 1028 + 1024;
            const float* sp = s + tid * 1024 + 768 + 253;
            __stcs(op + 0, sp[0]);
            __stcs(op + 1, sp[1]);
            __stcs(op + 2, sp[2]);
        }
        __syncthreads();
    }
}

extern "C" void kernel_launch(void* const* d_in, const int* in_sizes, int n_in,
                              void* d_out, int out_size) {
    const float* x      = (const float*)d_in[0];
    const float* feat   = (const float*)d_in[1];
    const float* queues = (const float*)d_in[2];
    const float* fc_h_w = (const float*)d_in[3];
    const float* fc_h_b = (const float*)d_in[4];
    const float* fc_c_w = (const float*)d_in[5];
    const float* fc_c_b = (const float*)d_in[6];
    const float* conv_w = (const float*)d_in[7];
    const float* conv_b = (const float*)d_in[8];
    const float* fc1_w  = (const float*)d_in[9];
    const float* fc1_b  = (const float*)d_in[10];
    const float* fc2_w  = (const float*)d_in[11];
    const float* fc2_b  = (const float*)d_in[12];
    float* out = (float*)d_out;

    prep_kernel<<<(NLAYERS * 32 * 128 + 255) / 256, 256>>>(conv_w, fc1_w);
    compute_kernel<<<64, 256>>>(x, feat, queues,
                                fc_h_w, fc_h_b, fc_c_w, fc_c_b,
                                conv_b, fc1_b, fc2_w, fc2_b, out);
    copy_kernel<<<NCOPYB, 256>>>(queues, out);
}

// round 5
// speedup vs baseline: 1.2677x; 1.2677x over previous
#include <cuda_runtime.h>
#include <stdint.h>

#define NLAYERS 24
#define BATCH   512
#define RDIM    32
#define LQ      256
#define LOUT    257
#define NROWS   (NLAYERS*BATCH*RDIM)      /* 393216 rows */
#define QOUT_ELEMS (NROWS*LOUT)           /* 101,056,512 */
#define QOUT4   (QOUT_ELEMS/4)            /* 25,264,128  */
#define NCOMPUTE 64                       /* 64 blocks x 8 warps = 512 batches */
#define NCOPYB   824                      /* 64+824 = 888 = 148 SMs x 6 blocks */
#define ILP      4
#define FULLMASK 0xffffffffu

// ---------------- scratch (static device globals; no allocation) ----------------
__device__ float2 g_wT   [NLAYERS*32*128];   // [l][j][row] -> (w_past, w_h)
__device__ float  g_f1T  [NLAYERS*32*128];   // [l][j][k]   (fc1 transposed)
__device__ float  g_skips[BATCH*NLAYERS*RDIM]; // [b][l*32+r]  1.5 MB

__device__ __forceinline__ float sigf(float v) { return 1.0f / (1.0f + __expf(-v)); }

// ---------------- K0: weight transposes for coalesced lane access ----------------
__global__ void prep_kernel(const float* __restrict__ conv_w,
                            const float* __restrict__ fc1_w) {
    int idx = blockIdx.x * blockDim.x + threadIdx.x;
    if (idx >= NLAYERS * 32 * 128) return;
    {
        // conv_w: [l][row(128)][j(32)][2]  (float2 index = (l*128+row)*32 + j)
        int l = idx / 4096, rem = idx & 4095, row = rem / 32, j = rem & 31;
        float2 v = ((const float2*)conv_w)[idx];
        g_wT[(l * 32 + j) * 128 + row] = v;
    }
    {
        // fc1_w: [k(128)][768];  dst [l][j][k], idx == (l*32+j)*128 + k
        int l = idx / 4096, rem = idx & 4095, j = rem >> 7, k = rem & 127;
        g_f1T[idx] = fc1_w[k * 768 + l * 32 + j];
    }
}

// ---------------- K1: fused recurrence + queue copy, 42-reg budget ----------------
__global__ void __launch_bounds__(256, 6) main_kernel(
    const float* __restrict__ x,      const float* __restrict__ feat,
    const float* __restrict__ queues,
    const float* __restrict__ fc_h_w, const float* __restrict__ fc_h_b,
    const float* __restrict__ fc_c_w, const float* __restrict__ fc_c_b,
    const float* __restrict__ conv_b,
    float* __restrict__ out)
{
    if (blockIdx.x < NCOMPUTE) {
        // ---- compute path: 1 warp = 1 batch; lane = R index; no fc1 here ----
        int warp = threadIdx.x >> 5;
        int lane = threadIdx.x & 31;
        int b    = blockIdx.x * 8 + warp;

        float h, c;
        {
            float ha = fc_h_b[lane], ca = fc_c_b[lane];
            #pragma unroll
            for (int i = 0; i < 9; i++) {
                float wh = fc_h_w[lane * 9 + i];
                float wc = fc_c_w[lane * 9 + i];
                float v  = (i == 0) ? x[b] : feat[b * 8 + i - 1];
                ha += wh * v; ca += wc * v;
            }
            h = tanhf(ha); c = tanhf(ca);
        }
        // h BEFORE layer 0 -> t=256 column of layer 0's queue rows
        out[BATCH + (size_t)((0 * BATCH + b) * RDIM + lane) * LOUT + 256] = h;

        float p = __ldg(queues + (size_t)((0 * BATCH + b) * RDIM + lane) * LQ + (LQ - 1));

        #pragma unroll 1
        for (int l = 0; l < NLAYERS; l++) {
            float pn = 0.f;
            if (l < NLAYERS - 1) {
                int dn = 1 << ((l + 1) & 7);
                pn = __ldg(queues + (size_t)(((l + 1) * BATCH + b) * RDIM + lane) * LQ + (LQ - dn));
            }

            float a0 = __ldg(conv_b + l * 128 +  0 + lane);
            float a1 = __ldg(conv_b + l * 128 + 32 + lane);
            float a2 = __ldg(conv_b + l * 128 + 64 + lane);
            float a3 = __ldg(conv_b + l * 128 + 96 + lane);

            const float2* wp = g_wT + l * 32 * 128;
            #pragma unroll 4
            for (int j = 0; j < 32; j++) {
                float pj = __shfl_sync(FULLMASK, p, j);
                float hj = __shfl_sync(FULLMASK, h, j);
                float2 w0 = wp[j * 128 +  0 + lane];
                float2 w1 = wp[j * 128 + 32 + lane];
                float2 w2 = wp[j * 128 + 64 + lane];
                float2 w3 = wp[j * 128 + 96 + lane];
                a0 += w0.x * pj + w0.y * hj;
                a1 += w1.x * pj + w1.y * hj;
                a2 += w2.x * pj + w2.y * hj;
                a3 += w3.x * pj + w3.y * hj;
            }
            c = sigf(a0) * c + tanhf(a1) * sigf(a2);
            h = sigf(a3) * tanhf(c);
            p = pn;

            // skip[l] = new h (for head kernel)
            g_skips[b * (NLAYERS * RDIM) + l * RDIM + lane] = h;

            if (l < NLAYERS - 1)
                out[BATCH + (size_t)(((l + 1) * BATCH + b) * RDIM + lane) * LOUT + 256] = h;
        }
    } else {
        // ---- copy path: gather-reads, dense float4 stores, ILP=4 ----
        const unsigned nthr = NCOPYB * 256u;
        unsigned t0 = (blockIdx.x - NCOMPUTE) * 256u + threadIdx.x;

        for (unsigned base = t0; base < (unsigned)QOUT4; base += nthr * ILP) {
            unsigned idx[ILP];
            float4   v[ILP];
            #pragma unroll
            for (int k = 0; k < ILP; k++) {
                unsigned i4 = base + (unsigned)k * nthr;
                idx[k] = i4;
                if (i4 < (unsigned)QOUT4) {
                    unsigned e   = i4 * 4u;
                    unsigned row = e / 257u;
                    unsigned t   = e - row * 257u;
                    if (t < 253u) {
                        const float* src = queues + (size_t)row * 256u + t;
                        v[k].x = __ldcs(src + 0);
                        v[k].y = __ldcs(src + 1);
                        v[k].z = __ldcs(src + 2);
                        v[k].w = __ldcs(src + 3);
                    }
                }
            }
            #pragma unroll
            for (int k = 0; k < ILP; k++) {
                unsigned i4 = idx[k];
                if (i4 >= (unsigned)QOUT4) continue;
                unsigned e   = i4 * 4u;
                unsigned row = e / 257u;
                unsigned t   = e - row * 257u;
                if (t < 253u) {
                    __stcs((float4*)(out + BATCH) + i4, v[k]);
                } else {
                    // row-wrap / t==256 slow path (t==256 owned by compute warps)
                    #pragma unroll
                    for (int j = 0; j < 4; j++) {
                        unsigned ee = e + (unsigned)j;
                        unsigned r2 = ee / 257u;
                        unsigned t2 = ee - r2 * 257u;
                        if (t2 < 256u) {
                            float val = __ldcs(queues + (size_t)r2 * 256u + t2);
                            __stcs(out + BATCH + ee, val);
                        }
                    }
                }
            }
        }
    }
}

// ---------------- K2: fc1 + relu + fc2 head (tiny) ----------------
__global__ void __launch_bounds__(128) head_kernel(
    const float* __restrict__ fc1_b, const float* __restrict__ fc2_w,
    const float* __restrict__ fc2_b, float* __restrict__ out)
{
    __shared__ float sk[NLAYERS * RDIM];   // 768 floats
    __shared__ float red[4];
    int b = blockIdx.x;
    int k = threadIdx.x;

    #pragma unroll
    for (int j = k; j < NLAYERS * RDIM; j += 128)
        sk[j] = g_skips[b * (NLAYERS * RDIM) + j];
    __syncthreads();

    float acc = fc1_b[k];
    #pragma unroll 8
    for (int j = 0; j < NLAYERS * RDIM; j++)
        acc += g_f1T[j * 128 + k] * sk[j];

    float r = fmaxf(acc, 0.f) * fc2_w[k];
    #pragma unroll
    for (int off = 16; off > 0; off >>= 1)
        r += __shfl_xor_sync(FULLMASK, r, off);
    if ((k & 31) == 0) red[k >> 5] = r;
    __syncthreads();
    if (k == 0)
        out[b] = red[0] + red[1] + red[2] + red[3] + fc2_b[0];
}

extern "C" void kernel_launch(void* const* d_in, const int* in_sizes, int n_in,
                              void* d_out, int out_size) {
    const float* x      = (const float*)d_in[0];
    const float* feat   = (const float*)d_in[1];
    const float* queues = (const float*)d_in[2];
    const float* fc_h_w = (const float*)d_in[3];
    const float* fc_h_b = (const float*)d_in[4];
    const float* fc_c_w = (const float*)d_in[5];
    const float* fc_c_b = (const float*)d_in[6];
    const float* conv_w = (const float*)d_in[7];
    const float* conv_b = (const float*)d_in[8];
    const float* fc1_w  = (const float*)d_in[9];
    const float* fc1_b  = (const float*)d_in[10];
    const float* fc2_w  = (const float*)d_in[11];
    const float* fc2_b  = (const float*)d_in[12];
    float* out = (float*)d_out;

    prep_kernel<<<(NLAYERS * 32 * 128 + 255) / 256, 256>>>(conv_w, fc1_w);
    main_kernel<<<NCOMPUTE + NCOPYB, 256>>>(x, feat, queues,
                                            fc_h_w, fc_h_b, fc_c_w, fc_c_b,
                                            conv_b, out);
    head_kernel<<<BATCH, 128>>>(fc1_b, fc2_w, fc2_b, out);
}